// round 1
// baseline (speedup 1.0000x reference)
#include <cuda_runtime.h>
#include <math.h>

#define SK        131072
#define S_SUB     16384
#define E_CNT     196608
#define H         128
#define N_TOT     4096
#define M_SUB     4
#define K_SUB     8
#define L_LAYERS  4
#define NUM_G     32

// ---------------- scratch (static device memory; no allocations) ----------------
__device__ float g_h[SK * H];     // node features (64 MB)
__device__ float g_aggr[SK * H];  // message aggregation buffer (64 MB)

// ---------------- kernels ----------------

__global__ void zero_aggr_kernel() {
    int i = blockIdx.x * blockDim.x + threadIdx.x;   // SK*H/4 threads
    ((float4*)g_aggr)[i] = make_float4(0.f, 0.f, 0.f, 0.f);
}

__global__ void embed_kernel(const int* __restrict__ x_tokens,
                             const int* __restrict__ node_ids,
                             const float* __restrict__ atom_emb,
                             const float* __restrict__ role_emb) {
    int t = blockIdx.x * blockDim.x + threadIdx.x;   // SK*32 threads (warp per node)
    int node = t >> 5;
    int lane = t & 31;
    int tok = x_tokens[node];
    float vf = (node_ids[node] >= 0) ? 1.0f : 0.0f;
    int is_root = ((node & (K_SUB - 1)) == 0) ? 1 : 0;
    int c = lane * 4;
    float4 a = *(const float4*)(&atom_emb[tok * H + c]);
    float4 r = *(const float4*)(&role_emb[is_root * H + c]);
    float4 o;
    o.x = (a.x + r.x) * vf;
    o.y = (a.y + r.y) * vf;
    o.z = (a.z + r.z) * vf;
    o.w = (a.w + r.w) * vf;
    *(float4*)(&g_h[node * H + c]) = o;
}

__global__ void edge_kernel(const int* __restrict__ src,
                            const int* __restrict__ dst,
                            const int* __restrict__ etok,
                            const float* __restrict__ bond_emb) {
    int t = blockIdx.x * blockDim.x + threadIdx.x;   // E*32 threads (warp per edge)
    int e = t >> 5;
    if (e >= E_CNT) return;
    int lane = t & 31;
    int s  = src[e];
    int d  = dst[e];
    int bt = etok[e];
    int c = lane * 4;
    float4 hv = *(const float4*)(&g_h[s * H + c]);
    float4 bv = *(const float4*)(&bond_emb[bt * H + c]);
    float4 m;
    m.x = fmaxf(hv.x + bv.x, 0.f);
    m.y = fmaxf(hv.y + bv.y, 0.f);
    m.z = fmaxf(hv.z + bv.z, 0.f);
    m.w = fmaxf(hv.w + bv.w, 0.f);
    float* zp = &g_aggr[d * H + c];
    atomicAdd(zp + 0, m.x);
    atomicAdd(zp + 1, m.y);
    atomicAdd(zp + 2, m.z);
    atomicAdd(zp + 3, m.w);
}

// Fused 2-GEMM MLP: h <- ( relu( ((1+eps)h + aggr) @ W1 + b1 ) @ W2 + b2 ) * vf
#define MLP_ROWS  64
#define ZS_STRIDE 132   // 128 + 4 pad: kills the 2-way LDS bank conflict on row reads
#define MLP_SMEM_FLOATS (MLP_ROWS * ZS_STRIDE + H * H + H)
#define MLP_SMEM_BYTES  (MLP_SMEM_FLOATS * 4)

__global__ __launch_bounds__(256, 2)
void mlp_kernel(const float* __restrict__ W1, const float* __restrict__ b1,
                const float* __restrict__ W2, const float* __restrict__ b2,
                const float* __restrict__ eps, int l,
                const int* __restrict__ node_ids) {
    extern __shared__ float smem[];
    float* zs = smem;                          // [64][132]
    float* ws = smem + MLP_ROWS * ZS_STRIDE;   // [128][128]
    float* bs = ws + H * H;                    // [128]

    const int tid  = threadIdx.x;
    const int row0 = blockIdx.x * MLP_ROWS;
    const float epsl = 1.0f + eps[l];

    // stage input tile: zs = (1+eps)*h + aggr
#pragma unroll
    for (int i = 0; i < 8; i++) {
        int idx = tid + i * 256;               // 2048 float4s
        int r = idx >> 5;
        int c = (idx & 31) << 2;
        float4 hv = *(const float4*)(&g_h[(row0 + r) * H + c]);
        float4 av = *(const float4*)(&g_aggr[(row0 + r) * H + c]);
        float4 z;
        z.x = epsl * hv.x + av.x;
        z.y = epsl * hv.y + av.y;
        z.z = epsl * hv.z + av.z;
        z.w = epsl * hv.w + av.w;
        *(float4*)(&zs[r * ZS_STRIDE + c]) = z;
    }
#pragma unroll
    for (int i = 0; i < 16; i++)
        ((float4*)ws)[tid + i * 256] = ((const float4*)W1)[tid + i * 256];
    if (tid < 32) ((float4*)bs)[tid] = ((const float4*)b1)[tid];
    __syncthreads();

    const int tx = tid & 15;     // 16 col-groups of 8
    const int ty = tid >> 4;     // 16 row-groups of 4
    float acc[4][8];

#define INIT_ACC()                                                  \
    _Pragma("unroll")                                               \
    for (int i = 0; i < 4; i++) {                                   \
        _Pragma("unroll")                                           \
        for (int j = 0; j < 8; j++) acc[i][j] = bs[tx * 8 + j];     \
    }

#define FMA_ROW(i, a)                                               \
    acc[i][0] += (a) * w0.x; acc[i][1] += (a) * w0.y;               \
    acc[i][2] += (a) * w0.z; acc[i][3] += (a) * w0.w;               \
    acc[i][4] += (a) * w1v.x; acc[i][5] += (a) * w1v.y;             \
    acc[i][6] += (a) * w1v.z; acc[i][7] += (a) * w1v.w;

#define GEMM_LOOP()                                                 \
    _Pragma("unroll 4")                                             \
    for (int k = 0; k < H; k++) {                                   \
        float a0 = zs[(ty * 4 + 0) * ZS_STRIDE + k];                \
        float a1 = zs[(ty * 4 + 1) * ZS_STRIDE + k];                \
        float a2 = zs[(ty * 4 + 2) * ZS_STRIDE + k];                \
        float a3 = zs[(ty * 4 + 3) * ZS_STRIDE + k];                \
        float4 w0  = *(float4*)(&ws[k * H + tx * 8]);               \
        float4 w1v = *(float4*)(&ws[k * H + tx * 8 + 4]);           \
        FMA_ROW(0, a0) FMA_ROW(1, a1) FMA_ROW(2, a2) FMA_ROW(3, a3) \
    }

    // GEMM 1
    INIT_ACC();
    GEMM_LOOP();
    __syncthreads();

    // relu -> zs; swap in W2/b2
#pragma unroll
    for (int i = 0; i < 4; i++) {
        *(float4*)(&zs[(ty * 4 + i) * ZS_STRIDE + tx * 8]) =
            make_float4(fmaxf(acc[i][0], 0.f), fmaxf(acc[i][1], 0.f),
                        fmaxf(acc[i][2], 0.f), fmaxf(acc[i][3], 0.f));
        *(float4*)(&zs[(ty * 4 + i) * ZS_STRIDE + tx * 8 + 4]) =
            make_float4(fmaxf(acc[i][4], 0.f), fmaxf(acc[i][5], 0.f),
                        fmaxf(acc[i][6], 0.f), fmaxf(acc[i][7], 0.f));
    }
#pragma unroll
    for (int i = 0; i < 16; i++)
        ((float4*)ws)[tid + i * 256] = ((const float4*)W2)[tid + i * 256];
    if (tid < 32) ((float4*)bs)[tid] = ((const float4*)b2)[tid];
    __syncthreads();

    // GEMM 2
    INIT_ACC();
    GEMM_LOOP();

    // store with validity re-mask
#pragma unroll
    for (int i = 0; i < 4; i++) {
        int r = row0 + ty * 4 + i;
        float vf = (node_ids[r] >= 0) ? 1.0f : 0.0f;
        *(float4*)(&g_h[r * H + tx * 8]) =
            make_float4(acc[i][0] * vf, acc[i][1] * vf, acc[i][2] * vf, acc[i][3] * vf);
        *(float4*)(&g_h[r * H + tx * 8 + 4]) =
            make_float4(acc[i][4] * vf, acc[i][5] * vf, acc[i][6] * vf, acc[i][7] * vf);
    }
#undef INIT_ACC
#undef FMA_ROW
#undef GEMM_LOOP
}

__global__ void zero_out_kernel(float* __restrict__ out, int n) {
    int i = blockIdx.x * blockDim.x + threadIdx.x;
    if (i < n) out[i] = 0.0f;
}

// per-canonical-node: scatter-mean per subgraph, HT softmax weighting, add-pool per graph
__global__ void pool_kernel(const int* __restrict__ node_ids,
                            const float* __restrict__ log_probs,
                            const int* __restrict__ batch_graph,
                            const float* __restrict__ ht_alpha,
                            float* __restrict__ out) {
    __shared__ float wgt[M_SUB];
    __shared__ float cinv[M_SUB];
    __shared__ int   nid_s[M_SUB * K_SUB];
    int n = blockIdx.x;
    int tid = threadIdx.x;

    if (tid < M_SUB * K_SUB) nid_s[tid] = node_ids[n * (M_SUB * K_SUB) + tid];
    __syncthreads();

    if (tid < M_SUB) {
        int c = 0;
#pragma unroll
        for (int kk = 0; kk < K_SUB; kk++) c += (nid_s[tid * K_SUB + kk] >= 0);
        cinv[tid] = 1.0f / fmaxf((float)c, 1.0f);
    }
    if (tid == 0) {
        float alpha = ht_alpha[0];
        float v[M_SUB];
        float mx = -3.4e38f;
#pragma unroll
        for (int mm = 0; mm < M_SUB; mm++) {
            float lp = log_probs[n * M_SUB + mm];
            if (!isfinite(lp)) lp = 0.0f;
            v[mm] = -alpha * lp;
            mx = fmaxf(mx, v[mm]);
        }
        float sum = 0.0f;
#pragma unroll
        for (int mm = 0; mm < M_SUB; mm++) { v[mm] = expf(v[mm] - mx); sum += v[mm]; }
#pragma unroll
        for (int mm = 0; mm < M_SUB; mm++) wgt[mm] = v[mm] / sum;
    }
    __syncthreads();

    int d = tid;  // 128 threads = H dims
    float val = 0.0f;
#pragma unroll
    for (int mm = 0; mm < M_SUB; mm++) {
        float s = 0.0f;
#pragma unroll
        for (int kk = 0; kk < K_SUB; kk++) {
            int fi = n * (M_SUB * K_SUB) + mm * K_SUB + kk;
            if (nid_s[mm * K_SUB + kk] >= 0) s += g_h[fi * H + d];
        }
        val += wgt[mm] * s * cinv[mm];
    }
    atomicAdd(&out[batch_graph[n] * H + d], val);
}

// ---------------- launch ----------------

extern "C" void kernel_launch(void* const* d_in, const int* in_sizes, int n_in,
                              void* d_out, int out_size) {
    const int*   x_tokens    = (const int*)d_in[0];
    const int*   edge_tokens = (const int*)d_in[1];
    const int*   intra_ei    = (const int*)d_in[2];   // [2, E] row-major
    const int*   node_ids    = (const int*)d_in[3];
    // d_in[4] = valid      (bool; derived from node_ids>=0 instead)
    // d_in[5] = sub_batch  (== i/8 by construction)
    const float* log_probs   = (const float*)d_in[6];
    const int*   batch_graph = (const int*)d_in[7];
    const float* atom_emb    = (const float*)d_in[8];
    const float* bond_emb    = (const float*)d_in[9];
    const float* role_emb    = (const float*)d_in[10];
    const float* eps         = (const float*)d_in[11];
    const float* w1          = (const float*)d_in[12];
    const float* b1          = (const float*)d_in[13];
    const float* w2          = (const float*)d_in[14];
    const float* b2          = (const float*)d_in[15];
    const float* ht_alpha    = (const float*)d_in[16];
    float* out = (float*)d_out;

    const int* src = intra_ei;
    const int* dst = intra_ei + E_CNT;

    cudaFuncSetAttribute(mlp_kernel, cudaFuncAttributeMaxDynamicSharedMemorySize,
                         MLP_SMEM_BYTES);

    embed_kernel<<<(SK * 32) / 256, 256>>>(x_tokens, node_ids, atom_emb, role_emb);

    for (int l = 0; l < L_LAYERS; l++) {
        zero_aggr_kernel<<<(SK * H / 4) / 256, 256>>>();
        edge_kernel<<<(E_CNT * 32) / 256, 256>>>(src, dst, edge_tokens, bond_emb);
        mlp_kernel<<<SK / MLP_ROWS, 256, MLP_SMEM_BYTES>>>(
            w1 + l * H * H, b1 + l * H, w2 + l * H * H, b2 + l * H,
            eps, l, node_ids);
    }

    zero_out_kernel<<<(NUM_G * H + 255) / 256, 256>>>(out, NUM_G * H);
    pool_kernel<<<N_TOT, H>>>(node_ids, log_probs, batch_graph, ht_alpha, out);
}